// round 9
// baseline (speedup 1.0000x reference)
#include <cuda_runtime.h>

#define FULLMASK 0xffffffffu

// scratch (allocation-free rule): 50331648 floats = ~201 MB, liveness-reused
static __device__ __align__(16) float g_buf[50331648];

// Buffer plan (each region reused once its last reader has run):
//   A [0,        8388608) : SEQ (transposed input)  -> CTX (attention out)
//   B [8388608, 16777216) : LN1 -> LN2 -> OUT2 (final seq-layout)
//   C [16777216,41943040) : XP (GRU input proj)     -> QKV
//   D [41943040,50331648) : SEQ1 (post-GRU residual, live to the end)
constexpr long long SEQ  = 0;
constexpr long long CTX  = 0;
constexpr long long LN1  = 8388608;
constexpr long long LN2  = 8388608;
constexpr long long OUT2 = 8388608;
constexpr long long XP   = 16777216;
constexpr long long QKV  = 16777216;
constexpr long long SEQ1 = 41943040;

__device__ __forceinline__ float sigf(float v) {
    return __fdividef(1.f, 1.f + __expf(-v));
}
__device__ __forceinline__ float tanhfast(float v) {
    float e = __expf(2.f * v);
    return 1.f - __fdividef(2.f, e + 1.f);
}

// --------------------------------------------------------------------------
// K1: transpose [B,C,T,F] -> [N=B*F,T,C] + LayerNorm1. block=(t,b).
// --------------------------------------------------------------------------
__global__ __launch_bounds__(256) void k1_transpose_ln(
    const float* __restrict__ x, const float* __restrict__ g,
    const float* __restrict__ b) {
    __shared__ float s[64 * 129];
    __shared__ float mean_s[64], rstd_s[64];
    int t = blockIdx.x, bb = blockIdx.y, tid = threadIdx.x;
    #pragma unroll
    for (int it = 0; it < 32; it++) {
        int idx = it * 256 + tid;
        int c = idx >> 6, f = idx & 63;
        s[f * 129 + c] = x[(((bb * 128 + c) * 512) + t) * 64 + f];
    }
    __syncthreads();
    {
        int row = tid >> 2, part = tid & 3;
        float sum = 0.f, sq = 0.f;
        #pragma unroll
        for (int jj = 0; jj < 32; jj++) {
            float v = s[row * 129 + part * 32 + jj];
            sum += v; sq += v * v;
        }
        sum += __shfl_xor_sync(FULLMASK, sum, 1);
        sq  += __shfl_xor_sync(FULLMASK, sq, 1);
        sum += __shfl_xor_sync(FULLMASK, sum, 2);
        sq  += __shfl_xor_sync(FULLMASK, sq, 2);
        if (part == 0) {
            float mean = sum * (1.f / 128.f);
            float var = sq * (1.f / 128.f) - mean * mean;
            mean_s[row] = mean;
            rstd_s[row] = rsqrtf(var + 1e-5f);
        }
    }
    __syncthreads();
    #pragma unroll
    for (int it = 0; it < 32; it++) {
        int idx = it * 256 + tid;
        int f = idx >> 7, c = idx & 127;
        float v = s[f * 129 + c];
        long long o = (long long)((bb * 64 + f) * 512 + t) * 128 + c;
        g_buf[SEQ + o] = v;
        g_buf[LN1 + o] = (v - mean_s[f]) * rstd_s[f] * g[c] + b[c];
    }
}

// --------------------------------------------------------------------------
// K2: GRU input projections: xp[row, g*96+e] = LN1[row, g*32+:32] . wih[e,:]
// block = 64 rows x one group.
// --------------------------------------------------------------------------
__global__ __launch_bounds__(256) void k2_xp(const float* __restrict__ wih,
                                             const float* __restrict__ bih) {
    __shared__ __align__(16) float As[32 * 68];
    __shared__ __align__(16) float Bs[32 * 100];
    int m0 = blockIdx.x * 64, gg = blockIdx.y, tid = threadIdx.x;
    const float* A = g_buf + LN1;
    #pragma unroll
    for (int it = 0; it < 8; it++) {
        int idx = it * 256 + tid;
        int r = idx >> 5, d = idx & 31;
        As[d * 68 + r] = A[(long long)(m0 + r) * 128 + gg * 32 + d];
    }
    #pragma unroll
    for (int it = 0; it < 12; it++) {
        int idx = it * 256 + tid;       // idx = e*32 + d
        int e = idx >> 5, d = idx & 31;
        Bs[d * 100 + e] = wih[idx];
    }
    __syncthreads();
    int ty = tid >> 4, tx = tid & 15;
    float acc[4][6];
    #pragma unroll
    for (int i = 0; i < 4; i++)
        #pragma unroll
        for (int j = 0; j < 6; j++) acc[i][j] = 0.f;
    #pragma unroll
    for (int d = 0; d < 32; d++) {
        float4 a = *(const float4*)&As[d * 68 + ty * 4];
        float2 b0 = *(const float2*)&Bs[d * 100 + tx * 6];
        float2 b1 = *(const float2*)&Bs[d * 100 + tx * 6 + 2];
        float2 b2 = *(const float2*)&Bs[d * 100 + tx * 6 + 4];
        float av[4] = {a.x, a.y, a.z, a.w};
        float bv[6] = {b0.x, b0.y, b1.x, b1.y, b2.x, b2.y};
        #pragma unroll
        for (int i = 0; i < 4; i++)
            #pragma unroll
            for (int j = 0; j < 6; j++)
                acc[i][j] = fmaf(av[i], bv[j], acc[i][j]);
    }
    float* O = g_buf + XP;
    #pragma unroll
    for (int i = 0; i < 4; i++) {
        long long row = m0 + ty * 4 + i;
        #pragma unroll
        for (int j = 0; j < 6; j++) {
            int e = tx * 6 + j;
            O[row * 384 + gg * 96 + e] = acc[i][j] + bih[e];
        }
    }
}

// --------------------------------------------------------------------------
// K3: GRU recurrence. One warp per (sequence n, group g). h one elem/lane.
// --------------------------------------------------------------------------
__device__ __forceinline__ void gru_pref4(float (&X)[4], float (&Z)[4],
                                          float (&Nb)[4], float (&Wb)[4],
                                          const float* xp, const float* sq,
                                          int tb) {
    #pragma unroll
    for (int u = 0; u < 4; u++) {
        X[u]  = xp[(tb + u) * 384];
        Z[u]  = xp[(tb + u) * 384 + 32];
        Nb[u] = xp[(tb + u) * 384 + 64];
        Wb[u] = sq[(tb + u) * 128];
    }
}

__device__ __forceinline__ void gru_proc4(float& h, const float (&wr)[32],
                                          const float (&wz)[32],
                                          const float (&wn)[32], float br,
                                          float bz, float bn,
                                          const float (&X)[4],
                                          const float (&Z)[4],
                                          const float (&Nb)[4],
                                          const float (&Wb)[4], float* sq1,
                                          int tb) {
    #pragma unroll
    for (int u = 0; u < 4; u++) {
        float ar = br, az = bz, an = bn;
        #pragma unroll
        for (int d = 0; d < 32; d++) {
            float hv = __shfl_sync(FULLMASK, h, d);
            ar = fmaf(wr[d], hv, ar);
            az = fmaf(wz[d], hv, az);
            an = fmaf(wn[d], hv, an);
        }
        float r = sigf(X[u] + ar);
        float z = sigf(Z[u] + az);
        float nv = tanhfast(Nb[u] + r * an);
        h = nv + z * (h - nv);
        sq1[(tb + u) * 128] = Wb[u] + h;
    }
}

__global__ __launch_bounds__(128) void k3_gru(const float* __restrict__ whh,
                                              const float* __restrict__ bhh) {
    int n = blockIdx.x;
    int g = threadIdx.x >> 5;
    int j = threadIdx.x & 31;
    float wr[32], wz[32], wn[32];
    #pragma unroll
    for (int d = 0; d < 32; d++) {
        wr[d] = __ldg(&whh[j * 32 + d]);
        wz[d] = __ldg(&whh[(32 + j) * 32 + d]);
        wn[d] = __ldg(&whh[(64 + j) * 32 + d]);
    }
    float br = bhh[j], bz = bhh[32 + j], bn = bhh[64 + j];
    const float* xp = g_buf + XP + (long long)n * 512 * 384 + g * 96 + j;
    const float* sq = g_buf + SEQ + (long long)n * 512 * 128 + g * 32 + j;
    float* sq1 = g_buf + SEQ1 + (long long)n * 512 * 128 + g * 32 + j;
    float h = 0.f;
    float AX[4], AZ[4], AN[4], AW[4], BX[4], BZ[4], BN[4], BW[4];
    gru_pref4(AX, AZ, AN, AW, xp, sq, 0);
    for (int tb = 0; tb < 512; tb += 8) {
        gru_pref4(BX, BZ, BN, BW, xp, sq, tb + 4);
        gru_proc4(h, wr, wz, wn, br, bz, bn, AX, AZ, AN, AW, sq1, tb);
        if (tb + 8 < 512) gru_pref4(AX, AZ, AN, AW, xp, sq, tb + 8);
        gru_proc4(h, wr, wz, wn, br, bz, bn, BX, BZ, BN, BW, sq1, tb + 4);
    }
}

// --------------------------------------------------------------------------
// K4: LayerNorm2. One row (n,t) per 128-thread block.
// --------------------------------------------------------------------------
__global__ __launch_bounds__(128) void k4_ln2(const float* __restrict__ g,
                                              const float* __restrict__ b) {
    long long row = blockIdx.x;
    int c = threadIdx.x;
    float v = g_buf[SEQ1 + row * 128 + c];
    float s = v, q = v * v;
    #pragma unroll
    for (int o = 16; o > 0; o >>= 1) {
        s += __shfl_xor_sync(FULLMASK, s, o);
        q += __shfl_xor_sync(FULLMASK, q, o);
    }
    __shared__ float ss[4], qq[4];
    if ((c & 31) == 0) { ss[c >> 5] = s; qq[c >> 5] = q; }
    __syncthreads();
    float S = ss[0] + ss[1] + ss[2] + ss[3];
    float Q = qq[0] + qq[1] + qq[2] + qq[3];
    float mean = S * (1.f / 128.f);
    float var = Q * (1.f / 128.f) - mean * mean;
    float rstd = rsqrtf(var + 1e-5f);
    g_buf[LN2 + row * 128 + c] = (v - mean) * rstd * g[c] + b[c];
}

// --------------------------------------------------------------------------
// Generic 64x64-tile SIMT GEMM: out[r,c] = A[r,:K].W[c,:K] + bias (+residual)
// --------------------------------------------------------------------------
template <int KTOT, int NTOT, long long AOFF, long long OOFF, long long ROFF>
__global__ __launch_bounds__(256) void gemm64(const float* __restrict__ W,
                                              const float* __restrict__ bias) {
    __shared__ __align__(16) float As[32 * 68];
    __shared__ __align__(16) float Bs[32 * 68];
    int m0 = blockIdx.x * 64, n0 = blockIdx.y * 64, tid = threadIdx.x;
    int ty = tid >> 4, tx = tid & 15;
    const float* A = g_buf + AOFF;
    float acc[4][4] = {{0.f}};
    for (int kc = 0; kc < KTOT; kc += 32) {
        __syncthreads();
        #pragma unroll
        for (int it = 0; it < 8; it++) {
            int idx = it * 256 + tid;
            int r = idx >> 5, k = idx & 31;
            As[k * 68 + r] = A[(long long)(m0 + r) * KTOT + kc + k];
            Bs[k * 68 + r] = W[(n0 + r) * KTOT + kc + k];
        }
        __syncthreads();
        #pragma unroll
        for (int k = 0; k < 32; k++) {
            float4 a = *(const float4*)&As[k * 68 + ty * 4];
            float4 bb = *(const float4*)&Bs[k * 68 + tx * 4];
            float av[4] = {a.x, a.y, a.z, a.w};
            float bv[4] = {bb.x, bb.y, bb.z, bb.w};
            #pragma unroll
            for (int i = 0; i < 4; i++)
                #pragma unroll
                for (int jj = 0; jj < 4; jj++)
                    acc[i][jj] = fmaf(av[i], bv[jj], acc[i][jj]);
        }
    }
    #pragma unroll
    for (int i = 0; i < 4; i++) {
        long long row = m0 + ty * 4 + i;
        #pragma unroll
        for (int jj = 0; jj < 4; jj++) {
            int col = n0 + tx * 4 + jj;
            float v = acc[i][jj] + bias[col];
            if constexpr (ROFF >= 0) v += g_buf[ROFF + row * NTOT + col];
            g_buf[OOFF + row * NTOT + col] = v;
        }
    }
}

// --------------------------------------------------------------------------
// K5: windowed causal flash attention. block = (n, head, q-tile of 64).
// keys limited to [q-100, q] -> at most 3 k-tiles of 64.
// --------------------------------------------------------------------------
__global__ __launch_bounds__(256) void k5_attn() {
    __shared__ __align__(16) float Qs[32 * 68];
    __shared__ __align__(16) float Ks[32 * 68];
    __shared__ __align__(16) float Vs[64 * 36];
    __shared__ __align__(16) float Ps[64 * 68];
    __shared__ float mrow[64], lrow[64], arow[64];
    int n = blockIdx.x, hh = blockIdx.y, qt = blockIdx.z;
    int q0 = qt * 64, tid = threadIdx.x;
    int ty = tid >> 4, tx = tid & 15;
    int qr = tid >> 2, part = tid & 3;        // softmax/PV mapping
    const float scale = 0.17677669529663687f; // 1/sqrt(32)
    const float* qkv = g_buf + QKV + (long long)n * 512 * 384;
    #pragma unroll
    for (int it = 0; it < 8; it++) {
        int idx = it * 256 + tid;
        int r = idx >> 5, d = idx & 31;
        Qs[d * 68 + r] = qkv[(q0 + r) * 384 + hh * 32 + d] * scale;
    }
    if (tid < 64) { mrow[tid] = -1e30f; lrow[tid] = 0.f; }
    float o[8];
    #pragma unroll
    for (int i = 0; i < 8; i++) o[i] = 0.f;
    int klo = q0 > 100 ? (q0 - 100) >> 6 : 0;
    for (int kt = klo; kt <= qt; kt++) {
        int k0 = kt * 64;
        __syncthreads();
        #pragma unroll
        for (int it = 0; it < 8; it++) {
            int idx = it * 256 + tid;
            int r = idx >> 5, d = idx & 31;
            int off = (k0 + r) * 384 + 128 + hh * 32 + d;
            Ks[d * 68 + r] = qkv[off];
            Vs[r * 36 + d] = qkv[off + 128];
        }
        __syncthreads();
        // scores
        float sacc[4][4] = {{0.f}};
        #pragma unroll
        for (int d = 0; d < 32; d++) {
            float4 a = *(const float4*)&Qs[d * 68 + ty * 4];
            float4 kk = *(const float4*)&Ks[d * 68 + tx * 4];
            float av[4] = {a.x, a.y, a.z, a.w};
            float bv[4] = {kk.x, kk.y, kk.z, kk.w};
            #pragma unroll
            for (int i = 0; i < 4; i++)
                #pragma unroll
                for (int jj = 0; jj < 4; jj++)
                    sacc[i][jj] = fmaf(av[i], bv[jj], sacc[i][jj]);
        }
        #pragma unroll
        for (int i = 0; i < 4; i++)
            #pragma unroll
            for (int jj = 0; jj < 4; jj++) {
                int qg = q0 + ty * 4 + i, kg = k0 + tx * 4 + jj;
                float sv = sacc[i][jj];
                if (kg > qg || qg - kg > 100) sv = -1e30f;
                Ps[(ty * 4 + i) * 68 + tx * 4 + jj] = sv;
            }
        __syncthreads();
        // online softmax: thread quad (qr, part) owns row qr, k-range part*16
        {
            float tm = -1e30f;
            #pragma unroll
            for (int u = 0; u < 16; u++)
                tm = fmaxf(tm, Ps[qr * 68 + part * 16 + u]);
            tm = fmaxf(tm, __shfl_xor_sync(FULLMASK, tm, 1));
            tm = fmaxf(tm, __shfl_xor_sync(FULLMASK, tm, 2));
            float mold = mrow[qr];
            float mnew = fmaxf(mold, tm);
            float psum = 0.f;
            #pragma unroll
            for (int u = 0; u < 16; u++) {
                float sv = Ps[qr * 68 + part * 16 + u];
                float p = (sv < -1e29f) ? 0.f : __expf(sv - mnew);
                Ps[qr * 68 + part * 16 + u] = p;
                psum += p;
            }
            psum += __shfl_xor_sync(FULLMASK, psum, 1);
            psum += __shfl_xor_sync(FULLMASK, psum, 2);
            if (part == 0) {
                float al = __expf(mold - mnew);
                mrow[qr] = mnew;
                lrow[qr] = lrow[qr] * al + psum;
                arow[qr] = al;
            }
        }
        __syncthreads();
        // PV: thread owns row qr, d-cols part*8..part*8+7
        {
            float al = arow[qr];
            #pragma unroll
            for (int i = 0; i < 8; i++) o[i] *= al;
            #pragma unroll
            for (int kk = 0; kk < 64; kk++) {
                float p = Ps[qr * 68 + kk];
                float4 v0 = *(const float4*)&Vs[kk * 36 + part * 8];
                float4 v1 = *(const float4*)&Vs[kk * 36 + part * 8 + 4];
                o[0] = fmaf(p, v0.x, o[0]);
                o[1] = fmaf(p, v0.y, o[1]);
                o[2] = fmaf(p, v0.z, o[2]);
                o[3] = fmaf(p, v0.w, o[3]);
                o[4] = fmaf(p, v1.x, o[4]);
                o[5] = fmaf(p, v1.y, o[5]);
                o[6] = fmaf(p, v1.z, o[6]);
                o[7] = fmaf(p, v1.w, o[7]);
            }
        }
    }
    __syncthreads();
    float inv = __fdividef(1.f, lrow[qr]);
    float* ctx = g_buf + CTX + (long long)(n * 512 + q0 + qr) * 128 + hh * 32 +
                 part * 8;
    #pragma unroll
    for (int i = 0; i < 8; i++) ctx[i] = o[i] * inv;
}

// --------------------------------------------------------------------------
// K6: transpose [N,T,C] back to [B,C,T,F]. block=(t,b).
// --------------------------------------------------------------------------
__global__ __launch_bounds__(256) void k6_transpose_out(float* __restrict__ y) {
    __shared__ float s[128 * 65];
    int t = blockIdx.x, bb = blockIdx.y, tid = threadIdx.x;
    #pragma unroll
    for (int it = 0; it < 32; it++) {
        int idx = it * 256 + tid;
        int f = idx >> 7, c = idx & 127;
        s[c * 65 + f] = g_buf[OUT2 + (long long)((bb * 64 + f) * 512 + t) * 128 + c];
    }
    __syncthreads();
    #pragma unroll
    for (int it = 0; it < 32; it++) {
        int idx = it * 256 + tid;
        int c = idx >> 6, f = idx & 63;
        y[(((bb * 128 + c) * 512) + t) * 64 + f] = s[c * 65 + f];
    }
}

// --------------------------------------------------------------------------
extern "C" void kernel_launch(void* const* d_in, const int* in_sizes, int n_in,
                              void* d_out, int out_size) {
    const float* x         = (const float*)d_in[0];
    const float* ln1_g     = (const float*)d_in[1];
    const float* ln1_b     = (const float*)d_in[2];
    const float* gru_wih   = (const float*)d_in[3];
    const float* gru_whh   = (const float*)d_in[4];
    const float* gru_bih   = (const float*)d_in[5];
    const float* gru_bhh   = (const float*)d_in[6];
    const float* ln2_g     = (const float*)d_in[7];
    const float* ln2_b     = (const float*)d_in[8];
    const float* in_proj_w = (const float*)d_in[9];
    const float* in_proj_b = (const float*)d_in[10];
    const float* out_proj_w= (const float*)d_in[11];
    const float* out_proj_b= (const float*)d_in[12];
    float* y = (float*)d_out;

    dim3 gT(512, 2);
    k1_transpose_ln<<<gT, 256>>>(x, ln1_g, ln1_b);
    dim3 gXP(1024, 4);
    k2_xp<<<gXP, 256>>>(gru_wih, gru_bih);
    k3_gru<<<128, 128>>>(gru_whh, gru_bhh);
    k4_ln2<<<65536, 128>>>(ln2_g, ln2_b);
    dim3 gQKV(1024, 6);
    gemm64<128, 384, LN2, QKV, -1LL><<<gQKV, 256>>>(in_proj_w, in_proj_b);
    dim3 gA(128, 4, 8);
    k5_attn<<<gA, 256>>>();
    dim3 gOP(1024, 2);
    gemm64<128, 128, CTX, OUT2, SEQ1><<<gOP, 256>>>(out_proj_w, out_proj_b);
    k6_transpose_out<<<gT, 256>>>(y);
}

// round 11
// speedup vs baseline: 1.7660x; 1.7660x over previous
#include <cuda_runtime.h>

#define FULLMASK 0xffffffffu

// scratch (allocation-free rule): 50331648 floats = ~201 MB, liveness-reused
static __device__ __align__(16) float g_buf[50331648];

constexpr long long SEQ  = 0;
constexpr long long CTX  = 0;
constexpr long long LN1  = 8388608;
constexpr long long LN2  = 8388608;
constexpr long long OUT2 = 8388608;
constexpr long long XP   = 16777216;
constexpr long long QKV  = 16777216;
constexpr long long SEQ1 = 41943040;

__device__ __forceinline__ float sigf(float v) {
    return __fdividef(1.f, 1.f + __expf(-v));
}
__device__ __forceinline__ float tanhfast(float v) {
    float e = __expf(2.f * v);
    return 1.f - __fdividef(2.f, e + 1.f);
}
__device__ __forceinline__ unsigned f2tf(float x) {
    unsigned r;
    asm("cvt.rna.tf32.f32 %0, %1;" : "=r"(r) : "f"(x));
    return r;
}
// D += A(16x8,row) * B(8x8,col)   tf32, fp32 accum
__device__ __forceinline__ void mma8(float* d, const unsigned* a,
                                     const unsigned* b) {
    asm volatile(
        "mma.sync.aligned.m16n8k8.row.col.f32.tf32.tf32.f32 "
        "{%0,%1,%2,%3},{%4,%5,%6,%7},{%8,%9},{%0,%1,%2,%3};"
        : "+f"(d[0]), "+f"(d[1]), "+f"(d[2]), "+f"(d[3])
        : "r"(a[0]), "r"(a[1]), "r"(a[2]), "r"(a[3]), "r"(b[0]), "r"(b[1]));
}

// --------------------------------------------------------------------------
// K1: transpose [B,C,T,F] -> [N=B*F,T,C] + LayerNorm1. block=(t,b).
// --------------------------------------------------------------------------
__global__ __launch_bounds__(256) void k1_transpose_ln(
    const float* __restrict__ x, const float* __restrict__ g,
    const float* __restrict__ b) {
    __shared__ float s[64 * 129];
    __shared__ float mean_s[64], rstd_s[64];
    int t = blockIdx.x, bb = blockIdx.y, tid = threadIdx.x;
    #pragma unroll
    for (int it = 0; it < 32; it++) {
        int idx = it * 256 + tid;
        int c = idx >> 6, f = idx & 63;
        s[f * 129 + c] = x[(((bb * 128 + c) * 512) + t) * 64 + f];
    }
    __syncthreads();
    {
        int row = tid >> 2, part = tid & 3;
        float sum = 0.f, sq = 0.f;
        #pragma unroll
        for (int jj = 0; jj < 32; jj++) {
            float v = s[row * 129 + part * 32 + jj];
            sum += v; sq += v * v;
        }
        sum += __shfl_xor_sync(FULLMASK, sum, 1);
        sq  += __shfl_xor_sync(FULLMASK, sq, 1);
        sum += __shfl_xor_sync(FULLMASK, sum, 2);
        sq  += __shfl_xor_sync(FULLMASK, sq, 2);
        if (part == 0) {
            float mean = sum * (1.f / 128.f);
            float var = sq * (1.f / 128.f) - mean * mean;
            mean_s[row] = mean;
            rstd_s[row] = rsqrtf(var + 1e-5f);
        }
    }
    __syncthreads();
    #pragma unroll
    for (int it = 0; it < 32; it++) {
        int idx = it * 256 + tid;
        int f = idx >> 7, c = idx & 127;
        float v = s[f * 129 + c];
        long long o = (long long)((bb * 64 + f) * 512 + t) * 128 + c;
        g_buf[SEQ + o] = v;
        g_buf[LN1 + o] = (v - mean_s[f]) * rstd_s[f] * g[c] + b[c];
    }
}

// --------------------------------------------------------------------------
// K2: GRU input projections (fp32 SIMT; keeps GRU path accurate)
// --------------------------------------------------------------------------
__global__ __launch_bounds__(256) void k2_xp(const float* __restrict__ wih,
                                             const float* __restrict__ bih) {
    __shared__ __align__(16) float As[32 * 68];
    __shared__ __align__(16) float Bs[32 * 100];
    int m0 = blockIdx.x * 64, gg = blockIdx.y, tid = threadIdx.x;
    const float* A = g_buf + LN1;
    #pragma unroll
    for (int it = 0; it < 8; it++) {
        int idx = it * 256 + tid;
        int r = idx >> 5, d = idx & 31;
        As[d * 68 + r] = A[(long long)(m0 + r) * 128 + gg * 32 + d];
    }
    #pragma unroll
    for (int it = 0; it < 12; it++) {
        int idx = it * 256 + tid;
        int e = idx >> 5, d = idx & 31;
        Bs[d * 100 + e] = wih[idx];
    }
    __syncthreads();
    int ty = tid >> 4, tx = tid & 15;
    float acc[4][6];
    #pragma unroll
    for (int i = 0; i < 4; i++)
        #pragma unroll
        for (int j = 0; j < 6; j++) acc[i][j] = 0.f;
    #pragma unroll
    for (int d = 0; d < 32; d++) {
        float4 a = *(const float4*)&As[d * 68 + ty * 4];
        float2 b0 = *(const float2*)&Bs[d * 100 + tx * 6];
        float2 b1 = *(const float2*)&Bs[d * 100 + tx * 6 + 2];
        float2 b2 = *(const float2*)&Bs[d * 100 + tx * 6 + 4];
        float av[4] = {a.x, a.y, a.z, a.w};
        float bv[6] = {b0.x, b0.y, b1.x, b1.y, b2.x, b2.y};
        #pragma unroll
        for (int i = 0; i < 4; i++)
            #pragma unroll
            for (int j = 0; j < 6; j++)
                acc[i][j] = fmaf(av[i], bv[j], acc[i][j]);
    }
    float* O = g_buf + XP;
    #pragma unroll
    for (int i = 0; i < 4; i++) {
        long long row = m0 + ty * 4 + i;
        #pragma unroll
        for (int j = 0; j < 6; j++) {
            int e = tx * 6 + j;
            O[row * 384 + gg * 96 + e] = acc[i][j] + bih[e];
        }
    }
}

// --------------------------------------------------------------------------
// K3: GRU recurrence. One warp per (sequence n, group g).
// --------------------------------------------------------------------------
__device__ __forceinline__ void gru_pref4(float (&X)[4], float (&Z)[4],
                                          float (&Nb)[4], float (&Wb)[4],
                                          const float* xp, const float* sq,
                                          int tb) {
    #pragma unroll
    for (int u = 0; u < 4; u++) {
        X[u]  = xp[(tb + u) * 384];
        Z[u]  = xp[(tb + u) * 384 + 32];
        Nb[u] = xp[(tb + u) * 384 + 64];
        Wb[u] = sq[(tb + u) * 128];
    }
}

__device__ __forceinline__ void gru_proc4(float& h, const float (&wr)[32],
                                          const float (&wz)[32],
                                          const float (&wn)[32], float br,
                                          float bz, float bn,
                                          const float (&X)[4],
                                          const float (&Z)[4],
                                          const float (&Nb)[4],
                                          const float (&Wb)[4], float* sq1,
                                          int tb) {
    #pragma unroll
    for (int u = 0; u < 4; u++) {
        float ar = br, az = bz, an = bn;
        #pragma unroll
        for (int d = 0; d < 32; d++) {
            float hv = __shfl_sync(FULLMASK, h, d);
            ar = fmaf(wr[d], hv, ar);
            az = fmaf(wz[d], hv, az);
            an = fmaf(wn[d], hv, an);
        }
        float r = sigf(X[u] + ar);
        float z = sigf(Z[u] + az);
        float nv = tanhfast(Nb[u] + r * an);
        h = nv + z * (h - nv);
        sq1[(tb + u) * 128] = Wb[u] + h;
    }
}

__global__ __launch_bounds__(128) void k3_gru(const float* __restrict__ whh,
                                              const float* __restrict__ bhh) {
    int n = blockIdx.x;
    int g = threadIdx.x >> 5;
    int j = threadIdx.x & 31;
    float wr[32], wz[32], wn[32];
    #pragma unroll
    for (int d = 0; d < 32; d++) {
        wr[d] = __ldg(&whh[j * 32 + d]);
        wz[d] = __ldg(&whh[(32 + j) * 32 + d]);
        wn[d] = __ldg(&whh[(64 + j) * 32 + d]);
    }
    float br = bhh[j], bz = bhh[32 + j], bn = bhh[64 + j];
    const float* xp = g_buf + XP + (long long)n * 512 * 384 + g * 96 + j;
    const float* sq = g_buf + SEQ + (long long)n * 512 * 128 + g * 32 + j;
    float* sq1 = g_buf + SEQ1 + (long long)n * 512 * 128 + g * 32 + j;
    float h = 0.f;
    float AX[4], AZ[4], AN[4], AW[4], BX[4], BZ[4], BN[4], BW[4];
    gru_pref4(AX, AZ, AN, AW, xp, sq, 0);
    for (int tb = 0; tb < 512; tb += 8) {
        gru_pref4(BX, BZ, BN, BW, xp, sq, tb + 4);
        gru_proc4(h, wr, wz, wn, br, bz, bn, AX, AZ, AN, AW, sq1, tb);
        if (tb + 8 < 512) gru_pref4(AX, AZ, AN, AW, xp, sq, tb + 8);
        gru_proc4(h, wr, wz, wn, br, bz, bn, BX, BZ, BN, BW, sq1, tb + 4);
    }
}

// --------------------------------------------------------------------------
// K4: LayerNorm2: warp-per-row, float4. block=256 (8 rows).
// --------------------------------------------------------------------------
__global__ __launch_bounds__(256) void k4_ln2(const float* __restrict__ g,
                                              const float* __restrict__ b) {
    int w = threadIdx.x >> 5, lane = threadIdx.x & 31;
    long long row = (long long)blockIdx.x * 8 + w;
    float4 v = *(const float4*)&g_buf[SEQ1 + row * 128 + lane * 4];
    float s = v.x + v.y + v.z + v.w;
    float q = v.x * v.x + v.y * v.y + v.z * v.z + v.w * v.w;
    #pragma unroll
    for (int o = 16; o > 0; o >>= 1) {
        s += __shfl_xor_sync(FULLMASK, s, o);
        q += __shfl_xor_sync(FULLMASK, q, o);
    }
    float mean = s * (1.f / 128.f);
    float var = q * (1.f / 128.f) - mean * mean;
    float rstd = rsqrtf(var + 1e-5f);
    float4 gg = *(const float4*)&g[lane * 4];
    float4 bb = *(const float4*)&b[lane * 4];
    float4 o4;
    o4.x = (v.x - mean) * rstd * gg.x + bb.x;
    o4.y = (v.y - mean) * rstd * gg.y + bb.y;
    o4.z = (v.z - mean) * rstd * gg.z + bb.z;
    o4.w = (v.w - mean) * rstd * gg.w + bb.w;
    *(float4*)&g_buf[LN2 + row * 128 + lane * 4] = o4;
}

// --------------------------------------------------------------------------
// tf32 tensor-core GEMM: out[r,c] = A[r,:K].W[c,:K] + bias (+residual)
// 64x64 block tile, 128 threads = 4 warps, warp tile 32x32 (m16n8k8).
// --------------------------------------------------------------------------
template <int KTOT, int NTOT, long long AOFF, long long OOFF, long long ROFF>
__global__ __launch_bounds__(128) void gemm_tc(const float* __restrict__ W,
                                               const float* __restrict__ bias) {
    __shared__ unsigned As[64 * 20];  // [row][k] stride 20
    __shared__ unsigned Ws[64 * 20];  // [col][k] stride 20
    int m0 = blockIdx.x * 64, n0 = blockIdx.y * 64, tid = threadIdx.x;
    int wid = tid >> 5, lane = tid & 31;
    int g = lane >> 2, tg = lane & 3;
    int wm = wid & 1, wn = wid >> 1;  // warp tile (wm*32, wn*32)
    const float* A = g_buf + AOFF;
    float d[2][4][4];
    #pragma unroll
    for (int mt = 0; mt < 2; mt++)
        #pragma unroll
        for (int nt = 0; nt < 4; nt++)
            #pragma unroll
            for (int i = 0; i < 4; i++) d[mt][nt][i] = 0.f;
    for (int kc = 0; kc < KTOT; kc += 16) {
        __syncthreads();
        #pragma unroll
        for (int i = 0; i < 2; i++) {
            int v = i * 128 + tid;
            int r = v >> 2, c4 = v & 3;
            float4 a4 = *(const float4*)&A[(long long)(m0 + r) * KTOT + kc + c4 * 4];
            As[r * 20 + c4 * 4 + 0] = f2tf(a4.x);
            As[r * 20 + c4 * 4 + 1] = f2tf(a4.y);
            As[r * 20 + c4 * 4 + 2] = f2tf(a4.z);
            As[r * 20 + c4 * 4 + 3] = f2tf(a4.w);
            float4 w4 = *(const float4*)&W[(n0 + r) * KTOT + kc + c4 * 4];
            Ws[r * 20 + c4 * 4 + 0] = f2tf(w4.x);
            Ws[r * 20 + c4 * 4 + 1] = f2tf(w4.y);
            Ws[r * 20 + c4 * 4 + 2] = f2tf(w4.z);
            Ws[r * 20 + c4 * 4 + 3] = f2tf(w4.w);
        }
        __syncthreads();
        #pragma unroll
        for (int k8 = 0; k8 < 2; k8++) {
            unsigned a[2][4];
            #pragma unroll
            for (int mt = 0; mt < 2; mt++) {
                int base = (wm * 32 + mt * 16 + g) * 20 + k8 * 8 + tg;
                a[mt][0] = As[base];
                a[mt][1] = As[base + 8 * 20];
                a[mt][2] = As[base + 4];
                a[mt][3] = As[base + 8 * 20 + 4];
            }
            #pragma unroll
            for (int nt = 0; nt < 4; nt++) {
                int base = (wn * 32 + nt * 8 + g) * 20 + k8 * 8 + tg;
                unsigned bf[2];
                bf[0] = Ws[base];
                bf[1] = Ws[base + 4];
                #pragma unroll
                for (int mt = 0; mt < 2; mt++) mma8(d[mt][nt], a[mt], bf);
            }
        }
    }
    #pragma unroll
    for (int mt = 0; mt < 2; mt++) {
        #pragma unroll
        for (int nt = 0; nt < 4; nt++) {
            #pragma unroll
            for (int half = 0; half < 2; half++) {
                long long row = m0 + wm * 32 + mt * 16 + g + half * 8;
                #pragma unroll
                for (int j = 0; j < 2; j++) {
                    int col = n0 + wn * 32 + nt * 8 + tg * 2 + j;
                    float v = d[mt][nt][half * 2 + j] + bias[col];
                    if constexpr (ROFF >= 0) v += g_buf[ROFF + row * NTOT + col];
                    g_buf[OOFF + row * NTOT + col] = v;
                }
            }
        }
    }
}

// --------------------------------------------------------------------------
// K5: windowed causal flash attention, tf32 tensor cores.
// block=(n, head, qtile 64), 128 threads = 4 warps, warp owns 16 q-rows.
// --------------------------------------------------------------------------
__global__ __launch_bounds__(128) void k5_attn_tc() {
    __shared__ unsigned Qs[64 * 36];  // [q][d]
    __shared__ unsigned Ks[64 * 36];  // [k][d]
    __shared__ unsigned Vs[32 * 68];  // [d][k]  (transposed)
    __shared__ unsigned Ps[64 * 68];  // [q][k]
    int n = blockIdx.x, hh = blockIdx.y, qt = blockIdx.z;
    int q0 = qt * 64, tid = threadIdx.x;
    int wid = tid >> 5, lane = tid & 31;
    int g = lane >> 2, tg = lane & 3;
    int qb = wid * 16;
    const float scale = 0.17677669529663687f;  // 1/sqrt(32)
    const float* qkv = g_buf + QKV + (long long)n * 512 * 384;
    #pragma unroll
    for (int i = 0; i < 4; i++) {
        int v = i * 128 + tid;
        int r = v >> 3, d4 = v & 7;
        float4 q4 = *(const float4*)&qkv[(q0 + r) * 384 + hh * 32 + d4 * 4];
        Qs[r * 36 + d4 * 4 + 0] = f2tf(q4.x * scale);
        Qs[r * 36 + d4 * 4 + 1] = f2tf(q4.y * scale);
        Qs[r * 36 + d4 * 4 + 2] = f2tf(q4.z * scale);
        Qs[r * 36 + d4 * 4 + 3] = f2tf(q4.w * scale);
    }
    float m0 = -1e30f, m1 = -1e30f, l0 = 0.f, l1 = 0.f;
    float o[4][4];
    #pragma unroll
    for (int nt = 0; nt < 4; nt++)
        #pragma unroll
        for (int i = 0; i < 4; i++) o[nt][i] = 0.f;
    int qg0 = q0 + qb + g, qg1 = qg0 + 8;
    int klo = q0 > 100 ? (q0 - 100) >> 6 : 0;
    for (int kt = klo; kt <= qt; kt++) {
        int k0 = kt * 64;
        __syncthreads();
        #pragma unroll
        for (int i = 0; i < 4; i++) {
            int v = i * 128 + tid;
            int r = v >> 3, d4 = v & 7;
            int off = (k0 + r) * 384 + 128 + hh * 32 + d4 * 4;
            float4 kk = *(const float4*)&qkv[off];
            Ks[r * 36 + d4 * 4 + 0] = f2tf(kk.x);
            Ks[r * 36 + d4 * 4 + 1] = f2tf(kk.y);
            Ks[r * 36 + d4 * 4 + 2] = f2tf(kk.z);
            Ks[r * 36 + d4 * 4 + 3] = f2tf(kk.w);
            float4 vv = *(const float4*)&qkv[off + 128];
            Vs[(d4 * 4 + 0) * 68 + r] = f2tf(vv.x);
            Vs[(d4 * 4 + 1) * 68 + r] = f2tf(vv.y);
            Vs[(d4 * 4 + 2) * 68 + r] = f2tf(vv.z);
            Vs[(d4 * 4 + 3) * 68 + r] = f2tf(vv.w);
        }
        __syncthreads();
        // S = Q * K^T   (warp: 16 q-rows x 64 k-cols)
        float s[8][4];
        #pragma unroll
        for (int nt = 0; nt < 8; nt++)
            #pragma unroll
            for (int i = 0; i < 4; i++) s[nt][i] = 0.f;
        #pragma unroll
        for (int k8 = 0; k8 < 4; k8++) {
            unsigned a[4];
            int qa = (qb + g) * 36 + k8 * 8 + tg;
            a[0] = Qs[qa];
            a[1] = Qs[qa + 8 * 36];
            a[2] = Qs[qa + 4];
            a[3] = Qs[qa + 8 * 36 + 4];
            #pragma unroll
            for (int nt = 0; nt < 8; nt++) {
                int kb = (nt * 8 + g) * 36 + k8 * 8 + tg;
                unsigned bf[2];
                bf[0] = Ks[kb];
                bf[1] = Ks[kb + 4];
                mma8(s[nt], a, bf);
            }
        }
        // mask + online softmax (rows qg0, qg1 owned by this thread's quad)
        float tm0 = -1e30f, tm1 = -1e30f;
        #pragma unroll
        for (int nt = 0; nt < 8; nt++)
            #pragma unroll
            for (int j = 0; j < 2; j++) {
                int col = k0 + nt * 8 + tg * 2 + j;
                if (col <= qg0 && qg0 - col <= 100) tm0 = fmaxf(tm0, s[nt][j]);
                if (col <= qg1 && qg1 - col <= 100)
                    tm1 = fmaxf(tm1, s[nt][2 + j]);
            }
        tm0 = fmaxf(tm0, __shfl_xor_sync(FULLMASK, tm0, 1));
        tm0 = fmaxf(tm0, __shfl_xor_sync(FULLMASK, tm0, 2));
        tm1 = fmaxf(tm1, __shfl_xor_sync(FULLMASK, tm1, 1));
        tm1 = fmaxf(tm1, __shfl_xor_sync(FULLMASK, tm1, 2));
        float m0n = fmaxf(m0, tm0), m1n = fmaxf(m1, tm1);
        float sc0 = __expf(m0 - m0n), sc1 = __expf(m1 - m1n);
        float ps0 = 0.f, ps1 = 0.f;
        #pragma unroll
        for (int nt = 0; nt < 8; nt++)
            #pragma unroll
            for (int j = 0; j < 2; j++) {
                int col = k0 + nt * 8 + tg * 2 + j;
                bool a0 = (col <= qg0) && (qg0 - col <= 100);
                bool a1 = (col <= qg1) && (qg1 - col <= 100);
                float p0 = a0 ? __expf(s[nt][j] - m0n) : 0.f;
                float p1 = a1 ? __expf(s[nt][2 + j] - m1n) : 0.f;
                ps0 += p0;
                ps1 += p1;
                int cc = nt * 8 + tg * 2 + j;
                Ps[(qb + g) * 68 + cc] = f2tf(p0);
                Ps[(qb + g + 8) * 68 + cc] = f2tf(p1);
            }
        ps0 += __shfl_xor_sync(FULLMASK, ps0, 1);
        ps0 += __shfl_xor_sync(FULLMASK, ps0, 2);
        ps1 += __shfl_xor_sync(FULLMASK, ps1, 1);
        ps1 += __shfl_xor_sync(FULLMASK, ps1, 2);
        l0 = l0 * sc0 + ps0;
        l1 = l1 * sc1 + ps1;
        m0 = m0n;
        m1 = m1n;
        #pragma unroll
        for (int nt = 0; nt < 4; nt++) {
            o[nt][0] *= sc0;
            o[nt][1] *= sc0;
            o[nt][2] *= sc1;
            o[nt][3] *= sc1;
        }
        __syncwarp();
        // O += P * V   (warp: 16 q-rows x 32 d-cols; Ps rows are warp-private)
        #pragma unroll
        for (int k8 = 0; k8 < 8; k8++) {
            unsigned a[4];
            int pa = (qb + g) * 68 + k8 * 8 + tg;
            a[0] = Ps[pa];
            a[1] = Ps[pa + 8 * 68];
            a[2] = Ps[pa + 4];
            a[3] = Ps[pa + 8 * 68 + 4];
            #pragma unroll
            for (int nt = 0; nt < 4; nt++) {
                int vb = (nt * 8 + g) * 68 + k8 * 8 + tg;
                unsigned bf[2];
                bf[0] = Vs[vb];
                bf[1] = Vs[vb + 4];
                mma8(o[nt], a, bf);
            }
        }
        __syncwarp();
    }
    float i0 = __fdividef(1.f, l0);
    float i1 = __fdividef(1.f, l1);
    float* c0 = g_buf + CTX + ((long long)n * 512 + qg0) * 128 + hh * 32;
    float* c1 = g_buf + CTX + ((long long)n * 512 + qg1) * 128 + hh * 32;
    #pragma unroll
    for (int nt = 0; nt < 4; nt++)
        #pragma unroll
        for (int j = 0; j < 2; j++) {
            int cc = nt * 8 + tg * 2 + j;
            c0[cc] = o[nt][j] * i0;
            c1[cc] = o[nt][2 + j] * i1;
        }
}

// --------------------------------------------------------------------------
// K6: transpose [N,T,C] back to [B,C,T,F]. block=(t,b).
// --------------------------------------------------------------------------
__global__ __launch_bounds__(256) void k6_transpose_out(float* __restrict__ y) {
    __shared__ float s[128 * 65];
    int t = blockIdx.x, bb = blockIdx.y, tid = threadIdx.x;
    #pragma unroll
    for (int it = 0; it < 32; it++) {
        int idx = it * 256 + tid;
        int f = idx >> 7, c = idx & 127;
        s[c * 65 + f] = g_buf[OUT2 + (long long)((bb * 64 + f) * 512 + t) * 128 + c];
    }
    __syncthreads();
    #pragma unroll
    for (int it = 0; it < 32; it++) {
        int idx = it * 256 + tid;
        int c = idx >> 6, f = idx & 63;
        y[(((bb * 128 + c) * 512) + t) * 64 + f] = s[c * 65 + f];
    }
}

// --------------------------------------------------------------------------
extern "C" void kernel_launch(void* const* d_in, const int* in_sizes, int n_in,
                              void* d_out, int out_size) {
    const float* x         = (const float*)d_in[0];
    const float* ln1_g     = (const float*)d_in[1];
    const float* ln1_b     = (const float*)d_in[2];
    const float* gru_wih   = (const float*)d_in[3];
    const float* gru_whh   = (const float*)d_in[4];
    const float* gru_bih   = (const float*)d_in[5];
    const float* gru_bhh   = (const float*)d_in[6];
    const float* ln2_g     = (const float*)d_in[7];
    const float* ln2_b     = (const float*)d_in[8];
    const float* in_proj_w = (const float*)d_in[9];
    const float* in_proj_b = (const float*)d_in[10];
    const float* out_proj_w= (const float*)d_in[11];
    const float* out_proj_b= (const float*)d_in[12];
    float* y = (float*)d_out;

    dim3 gT(512, 2);
    k1_transpose_ln<<<gT, 256>>>(x, ln1_g, ln1_b);
    dim3 gXP(1024, 4);
    k2_xp<<<gXP, 256>>>(gru_wih, gru_bih);
    k3_gru<<<128, 128>>>(gru_whh, gru_bhh);
    k4_ln2<<<8192, 256>>>(ln2_g, ln2_b);
    dim3 gQKV(1024, 6);
    gemm_tc<128, 384, LN2, QKV, -1LL><<<gQKV, 128>>>(in_proj_w, in_proj_b);
    dim3 gA(128, 4, 8);
    k5_attn_tc<<<gA, 128>>>();
    dim3 gOP(1024, 2);
    gemm_tc<128, 128, CTX, OUT2, SEQ1><<<gOP, 128>>>(out_proj_w, out_proj_b);
    k6_transpose_out<<<gT, 256>>>(y);
}